// round 4
// baseline (speedup 1.0000x reference)
#include <cuda_runtime.h>
#include <math.h>

#define NN   50000
#define NE   800000
#define DD   96
#define NW   192          // W0|W1 concatenated output width
#define NG   64
#define HID  256
#define OUTD 32
#define EPS  1e-5f

// ---------------- device scratch (static, no allocation) ----------------
__device__ __align__(16) float g_Wcat[DD * NW];    // [96 x 192] = [W0 | W1]
__device__ __align__(16) float g_Y[NN * NW];       // h @ [W0|W1]   (38.4 MB)
__device__ __align__(16) float g_H[NN * DD];       // node features (19.2 MB)
__device__ int   g_deg[NN];
__device__ int   g_cnt[NN];
__device__ int   g_off[NN + 1];
__device__ int   g_cur[NN];
__device__ float g_dinv[NN];
__device__ int   g_csr_src[NE];
__device__ float g_csr_w[NE];
__device__ float g_sum[DD];
__device__ float g_sq[DD];
__device__ float g_pool[NG * DD];
__device__ float g_pcnt[NG];
__device__ float g_h1[NG * HID];
__device__ int   g_ei_t;   // dtype code for edge_index: 0=i32 1=i64 2=f32 3=f64
__device__ int   g_b_t;    // dtype code for batch

// dtype-agnostic index load (code: 0=i32 1=i64 2=f32 3=f64)
__device__ __forceinline__ int ld_idx(const void* p, long i, int code) {
    switch (code) {
        case 1:  return (int)((const long long*)p)[i];
        case 2:  return (int)((const float*)p)[i];
        case 3:  return (int)((const double*)p)[i];
        default: return ((const int*)p)[i];
    }
}
__device__ __forceinline__ int clampi(int v, int hi) {  // [0, hi)
    v = v < 0 ? 0 : v;
    return v >= hi ? hi - 1 : v;
}

// Detect dtype of an index buffer holding n logical values in [0, limit).
// Samples are strided across the array; i64/f64 sampling stays below n/2
// elements so it never reads past a 4-byte-element buffer.
__device__ int detect_code(const void* p, long n, int limit) {
    // int64: value in range (implies high word zero)
    {
        long st = (n / 2) / 64;
        bool ok = true;
        for (int i = 0; i < 64 && ok; i++) {
            long long v = ((const long long*)p)[(long)i * st];
            if (v < 0 || v >= limit) ok = false;
        }
        if (ok) return 1;
    }
    // int32
    {
        long st = n / 64;
        bool ok = true;
        for (int i = 0; i < 64 && ok; i++) {
            int v = ((const int*)p)[(long)i * st];
            if (v < 0 || v >= limit) ok = false;
        }
        if (ok) return 0;
    }
    // float32: finite, integral, in range
    {
        long st = n / 64;
        bool ok = true;
        for (int i = 0; i < 64 && ok; i++) {
            float v = ((const float*)p)[(long)i * st];
            if (!(v >= 0.f) || v >= (float)limit || v != floorf(v)) ok = false;
        }
        if (ok) return 2;
    }
    return 3;  // float64 fallback
}

__global__ void k_detect(const void* ei, const void* batch) {
    if (threadIdx.x == 0) {
        g_ei_t = detect_code(ei, 2L * NE, NN);
        g_b_t  = detect_code(batch, (long)NN, NG);
    }
}

// ---------------- setup kernels ----------------
__global__ void k_init(const float* __restrict__ W0, const float* __restrict__ W1) {
    int i = blockIdx.x * blockDim.x + threadIdx.x;
    int stride = gridDim.x * blockDim.x;
    for (int t = i; t < NN; t += stride) { g_deg[t] = 0; g_cnt[t] = 0; }
    for (int t = i; t < DD * NW; t += stride) {
        int k = t / NW, j = t % NW;
        g_Wcat[t] = (j < DD) ? W0[k * DD + j] : W1[k * DD + (j - DD)];
    }
    for (int t = i; t < NG * DD; t += stride) g_pool[t] = 0.f;
    for (int t = i; t < NG; t += stride) g_pcnt[t] = 0.f;
}

__global__ void k_count(const void* __restrict__ ei) {
    int e = blockIdx.x * blockDim.x + threadIdx.x;
    if (e < NE) {
        int code = g_ei_t;
        int s = clampi(ld_idx(ei, e, code), NN);
        int d = clampi(ld_idx(ei, (long)NE + e, code), NN);
        atomicAdd(&g_deg[s], 1);
        atomicAdd(&g_cnt[d], 1);
    }
}

// single-block exclusive scan of g_cnt -> g_off/g_cur, plus dinv from g_deg
__global__ void k_scan(void) {
    __shared__ int ssum[1024];
    const int t = threadIdx.x;
    const int CH = (NN + 1023) / 1024;  // 49
    int base = t * CH;
    int local = 0;
    for (int i = 0; i < CH; i++) {
        int idx = base + i;
        if (idx < NN) local += g_cnt[idx];
    }
    ssum[t] = local;
    __syncthreads();
    for (int o = 1; o < 1024; o <<= 1) {
        int v = (t >= o) ? ssum[t - o] : 0;
        __syncthreads();
        ssum[t] += v;
        __syncthreads();
    }
    int run = ssum[t] - local;   // exclusive prefix
    for (int i = 0; i < CH; i++) {
        int idx = base + i;
        if (idx < NN) {
            g_off[idx] = run;
            g_cur[idx] = run;
            run += g_cnt[idx];
        }
    }
    if (t == 0) g_off[NN] = ssum[1023];
    for (int idx = t; idx < NN; idx += 1024) {
        int d = g_deg[idx];
        g_dinv[idx] = (d > 0) ? rsqrtf((float)d) : 0.f;
    }
}

__global__ void k_scatter(const void* __restrict__ ei) {
    int e = blockIdx.x * blockDim.x + threadIdx.x;
    if (e < NE) {
        int code = g_ei_t;
        int s = clampi(ld_idx(ei, e, code), NN);
        int d = clampi(ld_idx(ei, (long)NE + e, code), NN);
        int pos = atomicAdd(&g_cur[d], 1);
        g_csr_src[pos] = s;
        g_csr_w[pos] = -(g_dinv[s] * g_dinv[d]);
    }
}

// ---------------- per-layer kernels ----------------
// GEMM: Y[NN,192] = Hin[NN,96] @ Wcat[96,192]; also zeroes BN stats.
// Hin == nullptr -> read from g_H (layers 1..4).
#define BM 128
#define BN 64
#define KC 32
__global__ __launch_bounds__(256) void k_gemm(const float* __restrict__ Hin) {
    if (blockIdx.x == 0 && blockIdx.y == 0 && threadIdx.x < DD) {
        g_sum[threadIdx.x] = 0.f;
        g_sq[threadIdx.x] = 0.f;
    }
    const float* __restrict__ src = Hin ? Hin : (const float*)g_H;

    __shared__ __align__(16) float As[BM][KC + 1];
    __shared__ __align__(16) float Bs[KC][BN];
    const int tid = threadIdx.x;
    const int tx = tid & 15;
    const int ty = tid >> 4;
    const int row0 = blockIdx.x * BM;
    const int col0 = blockIdx.y * BN;

    float acc[8][4];
#pragma unroll
    for (int i = 0; i < 8; i++)
#pragma unroll
        for (int j = 0; j < 4; j++) acc[i][j] = 0.f;

    for (int kc = 0; kc < DD; kc += KC) {
#pragma unroll
        for (int v = 0; v < 4; v++) {
            int lin = tid * 4 + v;
            int r = lin >> 3;
            int c4 = (lin & 7) << 2;
            int grow = row0 + r;
            float4 val = make_float4(0.f, 0.f, 0.f, 0.f);
            if (grow < NN) val = *(const float4*)(src + (long)grow * DD + kc + c4);
            As[r][c4] = val.x; As[r][c4 + 1] = val.y;
            As[r][c4 + 2] = val.z; As[r][c4 + 3] = val.w;
        }
#pragma unroll
        for (int v = 0; v < 2; v++) {
            int lin = tid * 2 + v;
            int r = lin >> 4;
            int c4 = (lin & 15) << 2;
            *(float4*)&Bs[r][c4] = *(const float4*)(g_Wcat + (kc + r) * NW + col0 + c4);
        }
        __syncthreads();
#pragma unroll
        for (int kk = 0; kk < KC; kk++) {
            float4 bb = *(float4*)&Bs[kk][tx * 4];
#pragma unroll
            for (int i = 0; i < 8; i++) {
                float a = As[ty * 8 + i][kk];
                acc[i][0] = fmaf(a, bb.x, acc[i][0]);
                acc[i][1] = fmaf(a, bb.y, acc[i][1]);
                acc[i][2] = fmaf(a, bb.z, acc[i][2]);
                acc[i][3] = fmaf(a, bb.w, acc[i][3]);
            }
        }
        __syncthreads();
    }
#pragma unroll
    for (int i = 0; i < 8; i++) {
        int r = row0 + ty * 8 + i;
        if (r < NN) {
            *(float4*)(g_Y + (long)r * NW + col0 + tx * 4) =
                make_float4(acc[i][0], acc[i][1], acc[i][2], acc[i][3]);
        }
    }
}

// aggregation: H[n] = Y0[n] + b + sum_{e: dst=n} w_e * Y1[src_e]; + BN partial stats
__global__ __launch_bounds__(256) void k_aggr(const float* __restrict__ bias) {
    __shared__ float ss[DD], sq[DD];
    const int tid = threadIdx.x;
    if (tid < DD) { ss[tid] = 0.f; sq[tid] = 0.f; }
    __syncthreads();

    int n = (blockIdx.x * blockDim.x + tid) >> 5;  // warp per node
    int lane = tid & 31;
    if (n < NN) {
        const float* y = g_Y + (long)n * NW;
        float a0 = y[lane] + bias[lane];
        float a1 = y[lane + 32] + bias[lane + 32];
        float a2 = y[lane + 64] + bias[lane + 64];
        int s0 = g_off[n];
        int e0 = s0 + g_cnt[n];
        for (int e = s0; e < e0; e++) {
            int sn = g_csr_src[e];
            float w = g_csr_w[e];
            const float* y1 = g_Y + (long)sn * NW + DD;
            a0 = fmaf(w, y1[lane], a0);
            a1 = fmaf(w, y1[lane + 32], a1);
            a2 = fmaf(w, y1[lane + 64], a2);
        }
        float* h = g_H + (long)n * DD;
        h[lane] = a0; h[lane + 32] = a1; h[lane + 64] = a2;
        atomicAdd(&ss[lane], a0);       atomicAdd(&sq[lane], a0 * a0);
        atomicAdd(&ss[lane + 32], a1);  atomicAdd(&sq[lane + 32], a1 * a1);
        atomicAdd(&ss[lane + 64], a2);  atomicAdd(&sq[lane + 64], a2 * a2);
    }
    __syncthreads();
    if (tid < DD) {
        atomicAdd(&g_sum[tid], ss[tid]);
        atomicAdd(&g_sq[tid], sq[tid]);
    }
}

__global__ void k_bnrelu(const float* __restrict__ gamma, const float* __restrict__ beta) {
    int i = blockIdx.x * blockDim.x + threadIdx.x;
    int stride = gridDim.x * blockDim.x;
    const float invN = 1.0f / NN;
    for (int t = i; t < NN * DD; t += stride) {
        int c = t % DD;
        float m = g_sum[c] * invN;
        float var = g_sq[c] * invN - m * m;
        float sc = rsqrtf(var + EPS) * gamma[c];
        float v = (g_H[t] - m) * sc + beta[c];
        g_H[t] = v > 0.f ? v : 0.f;
    }
}

// pooled sums: batch is sorted, so run-length accumulate before atomics
__global__ void k_pool(const void* __restrict__ batch) {
    const int c = threadIdx.x;           // 96 threads
    const int n0 = blockIdx.x * 64;
    const int code = g_b_t;
    float acc = 0.f, cacc = 0.f;
    int curg = -1;
    for (int i = 0; i < 64; i++) {
        int n = n0 + i;
        if (n >= NN) break;
        int g = clampi(ld_idx(batch, n, code), NG);
        if (g != curg) {
            if (curg >= 0) {
                atomicAdd(&g_pool[curg * DD + c], acc);
                if (c == 0) atomicAdd(&g_pcnt[curg], cacc);
            }
            curg = g; acc = 0.f; cacc = 0.f;
        }
        acc += g_H[(long)n * DD + c];
        cacc += 1.f;
    }
    if (curg >= 0) {
        atomicAdd(&g_pool[curg * DD + c], acc);
        if (c == 0) atomicAdd(&g_pcnt[curg], cacc);
    }
}

// head: mean -> fc1 -> BN(256) -> relu -> fc2, one block of 256
__global__ __launch_bounds__(256) void k_mlp(
    const float* __restrict__ fc1W, const float* __restrict__ fc1b,
    const float* __restrict__ bg, const float* __restrict__ bb,
    const float* __restrict__ fc2W, const float* __restrict__ fc2b,
    float* __restrict__ out) {
    __shared__ float gm[NG * DD];  // 24 KB
    const int tid = threadIdx.x;
    for (int t = tid; t < NG * DD; t += 256) {
        int g = t / DD;
        float cnt = g_pcnt[g];
        cnt = cnt > 1.f ? cnt : 1.f;
        gm[t] = g_pool[t] / cnt;
    }
    __syncthreads();

    const int j = tid;  // fc1 column 0..255
    float col[NG];
#pragma unroll
    for (int i = 0; i < NG; i++) {
        float s = fc1b[j];
#pragma unroll
        for (int k = 0; k < DD; k++) s = fmaf(gm[i * DD + k], fc1W[k * HID + j], s);
        col[i] = s;
    }
    float m = 0.f;
#pragma unroll
    for (int i = 0; i < NG; i++) m += col[i];
    m *= (1.0f / NG);
    float v = 0.f;
#pragma unroll
    for (int i = 0; i < NG; i++) { float d = col[i] - m; v = fmaf(d, d, v); }
    v *= (1.0f / NG);
    float sc = rsqrtf(v + EPS) * bg[j];
    float sh = bb[j];
#pragma unroll
    for (int i = 0; i < NG; i++) {
        float val = (col[i] - m) * sc + sh;
        g_h1[i * HID + j] = val > 0.f ? val : 0.f;
    }
    __syncthreads();  // orders g_h1 writes within the (single) block

    // fc2: 64x32 = 2048 outputs, 8 per thread
#pragma unroll
    for (int u = 0; u < 8; u++) {
        int o = tid * 8 + u;
        int i = o >> 5;
        int k = o & 31;
        float s = fc2b[k];
        for (int j2 = 0; j2 < HID; j2++)
            s = fmaf(g_h1[i * HID + j2], fc2W[j2 * OUTD + k], s);
        out[o] = s;
    }
}

// ---------------- launch ----------------
extern "C" void kernel_launch(void* const* d_in, const int* in_sizes, int n_in,
                              void* d_out, int out_size) {
    const float* x     = (const float*)d_in[0];
    const void*  ei    = d_in[1];
    const void*  batch = d_in[2];
    const float* W0    = (const float*)d_in[3];
    const float* W1    = (const float*)d_in[4];
    const float* chebB = (const float*)d_in[5];
    const float* bnG   = (const float*)d_in[6];
    const float* bnB   = (const float*)d_in[7];
    const float* fc1W  = (const float*)d_in[8];
    const float* fc1b  = (const float*)d_in[9];
    const float* bnfG  = (const float*)d_in[10];
    const float* bnfB  = (const float*)d_in[11];
    const float* fc2W  = (const float*)d_in[12];
    const float* fc2b  = (const float*)d_in[13];
    float* out = (float*)d_out;
    (void)in_sizes; (void)n_in; (void)out_size;

    k_detect<<<1, 32>>>(ei, batch);
    k_init<<<256, 256>>>(W0, W1);
    k_count<<<(NE + 255) / 256, 256>>>(ei);
    k_scan<<<1, 1024>>>();
    k_scatter<<<(NE + 255) / 256, 256>>>(ei);

    for (int l = 0; l < 5; l++) {
        k_gemm<<<dim3((NN + BM - 1) / BM, NW / BN), 256>>>(l == 0 ? x : (const float*)0);
        k_aggr<<<(NN * 32 + 255) / 256, 256>>>(chebB);
        k_bnrelu<<<4096, 256>>>(bnG + l * DD, bnB + l * DD);
    }

    k_pool<<<(NN + 63) / 64, DD>>>(batch);
    k_mlp<<<1, 256>>>(fc1W, fc1b, bnfG, bnfB, fc2W, fc2b, out);
}

// round 5
// speedup vs baseline: 1.2248x; 1.2248x over previous
#include <cuda_runtime.h>
#include <math.h>

#define NN   50000
#define NE   800000
#define DD   96
#define NW   192          // W0|W1 concatenated output width
#define NG   64
#define HID  256
#define OUTD 32
#define EPS  1e-5f
#define NL   5
#define NTILE ((NN + 1023) / 1024)   // 49

// ---------------- device scratch (static, no allocation) ----------------
__device__ __align__(16) float g_Wcat[DD * NW];    // [96 x 192] = [W0 | W1]
__device__ __align__(16) float g_Y[NN * NW];       // h @ [W0|W1]
__device__ __align__(16) float g_H[NN * DD];       // node features (raw, pre-BN)
__device__ int   g_deg[NN];
__device__ int   g_cnt[NN];
__device__ int   g_off[NN];
__device__ int   g_cur[NN];
__device__ float g_dinv[NN];
__device__ int   g_csr_src[NE];
__device__ float g_csr_w[NE];
__device__ int   g_bsum[NTILE];
__device__ int   g_boff[NTILE];
__device__ float g_sum[NL * DD];     // per-layer BN stats
__device__ float g_sq[NL * DD];
__device__ float g_pool[NG * DD];
__device__ float g_pcnt[NG];
__device__ float g_h1[NG * HID];
__device__ int   g_ei_t;   // dtype code: 0=i32 1=i64 2=f32 3=f64
__device__ int   g_b_t;

__device__ __forceinline__ int ld_idx(const void* p, long i, int code) {
    switch (code) {
        case 1:  return (int)((const long long*)p)[i];
        case 2:  return (int)((const float*)p)[i];
        case 3:  return (int)((const double*)p)[i];
        default: return ((const int*)p)[i];
    }
}
__device__ __forceinline__ int clampi(int v, int hi) {
    v = v < 0 ? 0 : v;
    return v >= hi ? hi - 1 : v;
}

// ---------------- parallel dtype detect (64 threads) ----------------
__global__ void k_detect(const void* ei, const void* batch) {
    __shared__ int ok[6];  // [ei i64, ei i32, ei f32, b i64, b i32, b f32]
    const int t = threadIdx.x;
    if (t < 6) ok[t] = 1;
    __syncthreads();
    // edge_index: n = 2*NE values, limit NN
    {
        const long n = 2L * NE;
        long st64 = (n / 2) / 64, st = n / 64;
        long long v64 = ((const long long*)ei)[(long)t * st64];
        if (v64 < 0 || v64 >= NN) atomicAnd(&ok[0], 0);
        int v32 = ((const int*)ei)[(long)t * st];
        if (v32 < 0 || v32 >= NN) atomicAnd(&ok[1], 0);
        float vf = ((const float*)ei)[(long)t * st];
        if (!(vf >= 0.f) || vf >= (float)NN || vf != floorf(vf)) atomicAnd(&ok[2], 0);
    }
    // batch: n = NN values, limit NG
    {
        const long n = (long)NN;
        long st64 = (n / 2) / 64, st = n / 64;
        long long v64 = ((const long long*)batch)[(long)t * st64];
        if (v64 < 0 || v64 >= NG) atomicAnd(&ok[3], 0);
        int v32 = ((const int*)batch)[(long)t * st];
        if (v32 < 0 || v32 >= NG) atomicAnd(&ok[4], 0);
        float vf = ((const float*)batch)[(long)t * st];
        if (!(vf >= 0.f) || vf >= (float)NG || vf != floorf(vf)) atomicAnd(&ok[5], 0);
    }
    __syncthreads();
    if (t == 0) {
        g_ei_t = ok[0] ? 1 : (ok[1] ? 0 : (ok[2] ? 2 : 3));
        g_b_t  = ok[3] ? 1 : (ok[4] ? 0 : (ok[5] ? 2 : 3));
    }
}

// ---------------- setup ----------------
__global__ void k_init(const float* __restrict__ W0, const float* __restrict__ W1) {
    int i = blockIdx.x * blockDim.x + threadIdx.x;
    int stride = gridDim.x * blockDim.x;
    for (int t = i; t < NN; t += stride) { g_deg[t] = 0; g_cnt[t] = 0; }
    for (int t = i; t < DD * NW; t += stride) {
        int k = t / NW, j = t % NW;
        g_Wcat[t] = (j < DD) ? W0[k * DD + j] : W1[k * DD + (j - DD)];
    }
    for (int t = i; t < NG * DD; t += stride) g_pool[t] = 0.f;
    for (int t = i; t < NG; t += stride) g_pcnt[t] = 0.f;
    for (int t = i; t < NL * DD; t += stride) { g_sum[t] = 0.f; g_sq[t] = 0.f; }
}

__global__ void k_count(const void* __restrict__ ei) {
    int e = blockIdx.x * blockDim.x + threadIdx.x;
    if (e < NE) {
        int code = g_ei_t;
        int s = clampi(ld_idx(ei, e, code), NN);
        int d = clampi(ld_idx(ei, (long)NE + e, code), NN);
        atomicAdd(&g_deg[s], 1);
        atomicAdd(&g_cnt[d], 1);
    }
}

// grid scan, stage 1: per-tile (1024 elems) totals
__global__ void k_tilesum(void) {
    __shared__ int wsum[32];
    int idx = blockIdx.x * 1024 + threadIdx.x;
    int v = (idx < NN) ? g_cnt[idx] : 0;
    unsigned lane = threadIdx.x & 31, wid = threadIdx.x >> 5;
#pragma unroll
    for (int o = 16; o > 0; o >>= 1) v += __shfl_down_sync(0xffffffffu, v, o);
    if (lane == 0) wsum[wid] = v;
    __syncthreads();
    if (wid == 0) {
        int s = wsum[lane];
#pragma unroll
        for (int o = 16; o > 0; o >>= 1) s += __shfl_down_sync(0xffffffffu, s, o);
        if (lane == 0) g_bsum[blockIdx.x] = s;
    }
}

// stage 2: exclusive scan of 49 tile totals (1 warp x 2 passes = 64 threads)
__global__ void k_tilescan(void) {
    __shared__ int sh[64];
    int t = threadIdx.x;
    int v = (t < NTILE) ? g_bsum[t] : 0;
    sh[t] = v;
    __syncthreads();
    for (int o = 1; o < 64; o <<= 1) {
        int u = (t >= o) ? sh[t - o] : 0;
        __syncthreads();
        sh[t] += u;
        __syncthreads();
    }
    if (t < NTILE) g_boff[t] = sh[t] - v;  // exclusive
}

// stage 3: per-tile block scan + base -> offsets; also dinv
__global__ void k_offsets(void) {
    __shared__ int wsum[32];
    int idx = blockIdx.x * 1024 + threadIdx.x;
    int v = (idx < NN) ? g_cnt[idx] : 0;
    unsigned lane = threadIdx.x & 31, wid = threadIdx.x >> 5;
    int s = v;
#pragma unroll
    for (int o = 1; o < 32; o <<= 1) {
        int n = __shfl_up_sync(0xffffffffu, s, o);
        if (lane >= o) s += n;
    }
    if (lane == 31) wsum[wid] = s;
    __syncthreads();
    if (wid == 0) {
        int w = wsum[lane];
#pragma unroll
        for (int o = 1; o < 32; o <<= 1) {
            int n = __shfl_up_sync(0xffffffffu, w, o);
            if (lane >= o) w += n;
        }
        wsum[lane] = w;  // inclusive scan of warp totals
    }
    __syncthreads();
    int base = (wid > 0 ? wsum[wid - 1] : 0) + g_boff[blockIdx.x];
    if (idx < NN) {
        int excl = s - v + base;
        g_off[idx] = excl;
        g_cur[idx] = excl;
        int d = g_deg[idx];
        g_dinv[idx] = (d > 0) ? rsqrtf((float)d) : 0.f;
    }
}

__global__ void k_scatter(const void* __restrict__ ei) {
    int e = blockIdx.x * blockDim.x + threadIdx.x;
    if (e < NE) {
        int code = g_ei_t;
        int s = clampi(ld_idx(ei, e, code), NN);
        int d = clampi(ld_idx(ei, (long)NE + e, code), NN);
        int pos = atomicAdd(&g_cur[d], 1);
        g_csr_src[pos] = s;
        g_csr_w[pos] = -(g_dinv[s] * g_dinv[d]);
    }
}

// ---------------- per-layer kernels ----------------
// GEMM: Y = act(Hin) @ Wcat, where act = BN(layer-1)+ReLU for layer>=1.
// Hin == nullptr -> read g_H.
#define BM 128
#define BN 64
#define KC 32
__global__ __launch_bounds__(256) void k_gemm(const float* __restrict__ Hin,
                                              const float* __restrict__ gamma,
                                              const float* __restrict__ beta,
                                              int layer) {
    const float* __restrict__ src = Hin ? Hin : (const float*)g_H;
    const bool dobn = layer > 0;

    __shared__ __align__(16) float As[BM][KC + 1];
    __shared__ __align__(16) float Bs[KC][BN];
    __shared__ float sm_m[DD], sm_sc[DD], sm_be[DD];
    const int tid = threadIdx.x;
    if (dobn && tid < DD) {
        const float invN = 1.0f / NN;
        int sidx = (layer - 1) * DD + tid;
        float m = g_sum[sidx] * invN;
        float var = g_sq[sidx] * invN - m * m;
        sm_m[tid] = m;
        sm_sc[tid] = rsqrtf(var + EPS) * gamma[tid];
        sm_be[tid] = beta[tid];
    }
    __syncthreads();

    const int tx = tid & 15;
    const int ty = tid >> 4;
    const int row0 = blockIdx.x * BM;
    const int col0 = blockIdx.y * BN;

    float acc[8][4];
#pragma unroll
    for (int i = 0; i < 8; i++)
#pragma unroll
        for (int j = 0; j < 4; j++) acc[i][j] = 0.f;

    for (int kc = 0; kc < DD; kc += KC) {
#pragma unroll
        for (int v = 0; v < 4; v++) {
            int lin = tid * 4 + v;
            int r = lin >> 3;
            int c4 = (lin & 7) << 2;
            int grow = row0 + r;
            float4 val = make_float4(0.f, 0.f, 0.f, 0.f);
            if (grow < NN) val = *(const float4*)(src + (long)grow * DD + kc + c4);
            if (dobn) {
                int c = kc + c4;
                val.x = fmaxf((val.x - sm_m[c])     * sm_sc[c]     + sm_be[c],     0.f);
                val.y = fmaxf((val.y - sm_m[c + 1]) * sm_sc[c + 1] + sm_be[c + 1], 0.f);
                val.z = fmaxf((val.z - sm_m[c + 2]) * sm_sc[c + 2] + sm_be[c + 2], 0.f);
                val.w = fmaxf((val.w - sm_m[c + 3]) * sm_sc[c + 3] + sm_be[c + 3], 0.f);
            }
            As[r][c4] = val.x; As[r][c4 + 1] = val.y;
            As[r][c4 + 2] = val.z; As[r][c4 + 3] = val.w;
        }
#pragma unroll
        for (int v = 0; v < 2; v++) {
            int lin = tid * 2 + v;
            int r = lin >> 4;
            int c4 = (lin & 15) << 2;
            *(float4*)&Bs[r][c4] = *(const float4*)(g_Wcat + (kc + r) * NW + col0 + c4);
        }
        __syncthreads();
#pragma unroll
        for (int kk = 0; kk < KC; kk++) {
            float4 bb = *(float4*)&Bs[kk][tx * 4];
#pragma unroll
            for (int i = 0; i < 8; i++) {
                float a = As[ty * 8 + i][kk];
                acc[i][0] = fmaf(a, bb.x, acc[i][0]);
                acc[i][1] = fmaf(a, bb.y, acc[i][1]);
                acc[i][2] = fmaf(a, bb.z, acc[i][2]);
                acc[i][3] = fmaf(a, bb.w, acc[i][3]);
            }
        }
        __syncthreads();
    }
#pragma unroll
    for (int i = 0; i < 8; i++) {
        int r = row0 + ty * 8 + i;
        if (r < NN) {
            *(float4*)(g_Y + (long)r * NW + col0 + tx * 4) =
                make_float4(acc[i][0], acc[i][1], acc[i][2], acc[i][3]);
        }
    }
}

// aggregation: H[n] = Y0[n] + b + sum_{e: dst=n} w_e * Y1[src_e]; BN stats -> layer l
__global__ __launch_bounds__(256) void k_aggr(const float* __restrict__ bias, int layer) {
    __shared__ float ss[DD], sq[DD];
    const int tid = threadIdx.x;
    if (tid < DD) { ss[tid] = 0.f; sq[tid] = 0.f; }
    __syncthreads();

    int n = (blockIdx.x * blockDim.x + tid) >> 5;  // warp per node
    int lane = tid & 31;
    if (n < NN) {
        const float* y = g_Y + (long)n * NW;
        float a0 = y[lane] + bias[lane];
        float a1 = y[lane + 32] + bias[lane + 32];
        float a2 = y[lane + 64] + bias[lane + 64];
        int s0 = g_off[n];
        int e0 = s0 + g_cnt[n];
        for (int e = s0; e < e0; e++) {
            int sn = g_csr_src[e];
            float w = g_csr_w[e];
            const float* y1 = g_Y + (long)sn * NW + DD;
            a0 = fmaf(w, y1[lane], a0);
            a1 = fmaf(w, y1[lane + 32], a1);
            a2 = fmaf(w, y1[lane + 64], a2);
        }
        float* h = g_H + (long)n * DD;
        h[lane] = a0; h[lane + 32] = a1; h[lane + 64] = a2;
        atomicAdd(&ss[lane], a0);       atomicAdd(&sq[lane], a0 * a0);
        atomicAdd(&ss[lane + 32], a1);  atomicAdd(&sq[lane + 32], a1 * a1);
        atomicAdd(&ss[lane + 64], a2);  atomicAdd(&sq[lane + 64], a2 * a2);
    }
    __syncthreads();
    if (tid < DD) {
        atomicAdd(&g_sum[layer * DD + tid], ss[tid]);
        atomicAdd(&g_sq[layer * DD + tid], sq[tid]);
    }
}

// pool: applies layer-4 BN+ReLU on the fly; batch sorted -> run-length accumulate
__global__ void k_pool(const void* __restrict__ batch,
                       const float* __restrict__ gamma,
                       const float* __restrict__ beta) {
    const int c = threadIdx.x;           // 96 threads
    const int n0 = blockIdx.x * 64;
    const int code = g_b_t;
    const float invN = 1.0f / NN;
    float m = g_sum[4 * DD + c] * invN;
    float var = g_sq[4 * DD + c] * invN - m * m;
    float sc = rsqrtf(var + EPS) * gamma[c];
    float be = beta[c];

    float acc = 0.f, cacc = 0.f;
    int curg = -1;
    for (int i = 0; i < 64; i++) {
        int n = n0 + i;
        if (n >= NN) break;
        int g = clampi(ld_idx(batch, n, code), NG);
        if (g != curg) {
            if (curg >= 0) {
                atomicAdd(&g_pool[curg * DD + c], acc);
                if (c == 0) atomicAdd(&g_pcnt[curg], cacc);
            }
            curg = g; acc = 0.f; cacc = 0.f;
        }
        float v = (g_H[(long)n * DD + c] - m) * sc + be;
        acc += v > 0.f ? v : 0.f;
        cacc += 1.f;
    }
    if (curg >= 0) {
        atomicAdd(&g_pool[curg * DD + c], acc);
        if (c == 0) atomicAdd(&g_pcnt[curg], cacc);
    }
}

// head: mean -> fc1 -> BN(256) -> relu -> fc2, one block of 256
__global__ __launch_bounds__(256) void k_mlp(
    const float* __restrict__ fc1W, const float* __restrict__ fc1b,
    const float* __restrict__ bg, const float* __restrict__ bb,
    const float* __restrict__ fc2W, const float* __restrict__ fc2b,
    float* __restrict__ out) {
    __shared__ float gm[NG * DD];  // 24 KB
    const int tid = threadIdx.x;
    for (int t = tid; t < NG * DD; t += 256) {
        int g = t / DD;
        float cnt = g_pcnt[g];
        cnt = cnt > 1.f ? cnt : 1.f;
        gm[t] = g_pool[t] / cnt;
    }
    __syncthreads();

    const int j = tid;
    float col[NG];
#pragma unroll
    for (int i = 0; i < NG; i++) {
        float s = fc1b[j];
#pragma unroll
        for (int k = 0; k < DD; k++) s = fmaf(gm[i * DD + k], fc1W[k * HID + j], s);
        col[i] = s;
    }
    float m = 0.f;
#pragma unroll
    for (int i = 0; i < NG; i++) m += col[i];
    m *= (1.0f / NG);
    float v = 0.f;
#pragma unroll
    for (int i = 0; i < NG; i++) { float d = col[i] - m; v = fmaf(d, d, v); }
    v *= (1.0f / NG);
    float sc = rsqrtf(v + EPS) * bg[j];
    float sh = bb[j];
#pragma unroll
    for (int i = 0; i < NG; i++) {
        float val = (col[i] - m) * sc + sh;
        g_h1[i * HID + j] = val > 0.f ? val : 0.f;
    }
    __syncthreads();

#pragma unroll
    for (int u = 0; u < 8; u++) {
        int o = tid * 8 + u;
        int i = o >> 5;
        int k = o & 31;
        float s = fc2b[k];
        for (int j2 = 0; j2 < HID; j2++)
            s = fmaf(g_h1[i * HID + j2], fc2W[j2 * OUTD + k], s);
        out[o] = s;
    }
}

// ---------------- launch ----------------
extern "C" void kernel_launch(void* const* d_in, const int* in_sizes, int n_in,
                              void* d_out, int out_size) {
    const float* x     = (const float*)d_in[0];
    const void*  ei    = d_in[1];
    const void*  batch = d_in[2];
    const float* W0    = (const float*)d_in[3];
    const float* W1    = (const float*)d_in[4];
    const float* chebB = (const float*)d_in[5];
    const float* bnG   = (const float*)d_in[6];
    const float* bnB   = (const float*)d_in[7];
    const float* fc1W  = (const float*)d_in[8];
    const float* fc1b  = (const float*)d_in[9];
    const float* bnfG  = (const float*)d_in[10];
    const float* bnfB  = (const float*)d_in[11];
    const float* fc2W  = (const float*)d_in[12];
    const float* fc2b  = (const float*)d_in[13];
    float* out = (float*)d_out;
    (void)in_sizes; (void)n_in; (void)out_size;

    k_detect<<<1, 64>>>(ei, batch);
    k_init<<<256, 256>>>(W0, W1);
    k_count<<<(NE + 255) / 256, 256>>>(ei);
    k_tilesum<<<NTILE, 1024>>>();
    k_tilescan<<<1, 64>>>();
    k_offsets<<<NTILE, 1024>>>();
    k_scatter<<<(NE + 255) / 256, 256>>>(ei);

    for (int l = 0; l < NL; l++) {
        k_gemm<<<dim3((NN + BM - 1) / BM, NW / BN), 256>>>(
            l == 0 ? x : (const float*)0,
            l > 0 ? bnG + (l - 1) * DD : (const float*)0,
            l > 0 ? bnB + (l - 1) * DD : (const float*)0, l);
        k_aggr<<<(NN * 32 + 255) / 256, 256>>>(chebB, l);
    }

    k_pool<<<(NN + 63) / 64, DD>>>(batch, bnG + 4 * DD, bnB + 4 * DD);
    k_mlp<<<1, 256>>>(fc1W, fc1b, bnfG, bnfB, fc2W, fc2b, out);
}